// round 1
// baseline (speedup 1.0000x reference)
#include <cuda_runtime.h>
#include <cuda_bf16.h>

#define MAX_NODES 100000
#define D 64

// Scratch: device globals (no allocation allowed in kernel_launch).
__device__ float g_agg[MAX_NODES * D];
__device__ float g_h[MAX_NODES * D];
__device__ float g_cnt[MAX_NODES];

// ---------------------------------------------------------------------------
// Zero a float buffer (float4 vectorized; n must be a multiple of 4)
// ---------------------------------------------------------------------------
__global__ void zero_kernel(float4* __restrict__ p, int n4) {
    int i = blockIdx.x * blockDim.x + threadIdx.x;
    if (i < n4) p[i] = make_float4(0.f, 0.f, 0.f, 0.f);
}

// ---------------------------------------------------------------------------
// Scatter: for each edge e, agg[dst] += x[src] (row of 64 floats).
// 16 threads per edge, each handles one float4 chunk.
// Lane 0 additionally accumulates degree count (layer 1 only).
// ---------------------------------------------------------------------------
__global__ void scatter_kernel(const float4* __restrict__ xin4,
                               const int* __restrict__ ei,
                               float* __restrict__ agg,
                               float* __restrict__ cnt,
                               int E, int do_count) {
    int tid = blockIdx.x * blockDim.x + threadIdx.x;
    int e = tid >> 4;
    if (e >= E) return;
    int j = tid & 15;
    int src = ei[e];
    int dst = ei[E + e];

    float4 v = xin4[src * 16 + j];
    float* p = &agg[dst * D + j * 4];
    asm volatile("red.global.add.v4.f32 [%0], {%1, %2, %3, %4};"
                 :: "l"(p), "f"(v.x), "f"(v.y), "f"(v.z), "f"(v.w)
                 : "memory");

    if (do_count && j == 0) {
        float one = 1.0f;
        asm volatile("red.global.add.f32 [%0], %1;"
                     :: "l"(&cnt[dst]), "f"(one)
                     : "memory");
    }
}

// ---------------------------------------------------------------------------
// Transform: out[i] = act( (agg[i]/max(cnt[i],1)) @ W_l + b_l + xin[i] @ W_r )
// 16 nodes per block, 128 threads. Each thread: 2 nodes x 4 output cols.
// W_l, W_r staged in smem (32KB), node rows staged in smem (8KB).
// ---------------------------------------------------------------------------
__global__ __launch_bounds__(128)
void transform_kernel(const float* __restrict__ xin,
                      const float* __restrict__ agg,
                      const float* __restrict__ cnt,
                      const float* __restrict__ Wl,
                      const float* __restrict__ bl,
                      const float* __restrict__ Wr,
                      float* __restrict__ out,
                      int n, int do_relu) {
    __shared__ float sWl[D * D];   // 16 KB
    __shared__ float sWr[D * D];   // 16 KB
    __shared__ float sM[16 * D];   // 4 KB  (mean rows)
    __shared__ float sX[16 * D];   // 4 KB  (input rows)
    __shared__ float sB[D];

    int t = threadIdx.x;  // 0..127
    // Stage weights: 4096 floats each = 1024 float4.
    for (int i = t; i < 1024; i += 128) {
        ((float4*)sWl)[i] = ((const float4*)Wl)[i];
        ((float4*)sWr)[i] = ((const float4*)Wr)[i];
    }
    if (t < D) sB[t] = bl[t];

    int base = blockIdx.x * 16;
    // Stage node rows: 16 nodes x 16 float4 = 256 float4 per array.
    for (int i = t; i < 256; i += 128) {
        int local = i >> 4;        // node within block
        int j = i & 15;            // float4 chunk within row
        int node = base + local;
        if (node < n) {
            float c = cnt[node];
            float inv = 1.0f / fmaxf(c, 1.0f);
            float4 a = ((const float4*)agg)[node * 16 + j];
            a.x *= inv; a.y *= inv; a.z *= inv; a.w *= inv;
            ((float4*)sM)[i] = a;
            ((float4*)sX)[i] = ((const float4*)xin)[node * 16 + j];
        } else {
            ((float4*)sM)[i] = make_float4(0.f, 0.f, 0.f, 0.f);
            ((float4*)sX)[i] = make_float4(0.f, 0.f, 0.f, 0.f);
        }
    }
    __syncthreads();

    int cg = t & 15;   // column group -> cols 4*cg .. 4*cg+3
    int nd = t >> 4;   // 0..7; handles nodes nd and nd+8
    int c0 = cg * 4;
    int n0 = nd, n1 = nd + 8;

    float4 bias = *(float4*)&sB[c0];
    float4 acc0 = bias;
    float4 acc1 = bias;

#pragma unroll
    for (int k = 0; k < D; k++) {
        float4 wl = *(float4*)&sWl[k * D + c0];
        float4 wr = *(float4*)&sWr[k * D + c0];
        float m0 = sM[n0 * D + k];
        float x0 = sX[n0 * D + k];
        float m1 = sM[n1 * D + k];
        float x1 = sX[n1 * D + k];
        acc0.x = fmaf(m0, wl.x, acc0.x); acc0.x = fmaf(x0, wr.x, acc0.x);
        acc0.y = fmaf(m0, wl.y, acc0.y); acc0.y = fmaf(x0, wr.y, acc0.y);
        acc0.z = fmaf(m0, wl.z, acc0.z); acc0.z = fmaf(x0, wr.z, acc0.z);
        acc0.w = fmaf(m0, wl.w, acc0.w); acc0.w = fmaf(x0, wr.w, acc0.w);
        acc1.x = fmaf(m1, wl.x, acc1.x); acc1.x = fmaf(x1, wr.x, acc1.x);
        acc1.y = fmaf(m1, wl.y, acc1.y); acc1.y = fmaf(x1, wr.y, acc1.y);
        acc1.z = fmaf(m1, wl.z, acc1.z); acc1.z = fmaf(x1, wr.z, acc1.z);
        acc1.w = fmaf(m1, wl.w, acc1.w); acc1.w = fmaf(x1, wr.w, acc1.w);
    }

    if (do_relu) {
        acc0.x = fmaxf(acc0.x, 0.f); acc0.y = fmaxf(acc0.y, 0.f);
        acc0.z = fmaxf(acc0.z, 0.f); acc0.w = fmaxf(acc0.w, 0.f);
        acc1.x = fmaxf(acc1.x, 0.f); acc1.y = fmaxf(acc1.y, 0.f);
        acc1.z = fmaxf(acc1.z, 0.f); acc1.w = fmaxf(acc1.w, 0.f);
    }

    int node0 = base + n0;
    int node1 = base + n1;
    if (node0 < n) *(float4*)&out[node0 * D + c0] = acc0;
    if (node1 < n) *(float4*)&out[node1 * D + c0] = acc1;
}

// ---------------------------------------------------------------------------
// Launch: layer1 = zero agg+cnt; scatter(x)+count; transform(x -> h, relu)
//         layer2 = zero agg;     scatter(h);       transform(h -> out)
// ---------------------------------------------------------------------------
extern "C" void kernel_launch(void* const* d_in, const int* in_sizes, int n_in,
                              void* d_out, int out_size) {
    const float* x   = (const float*)d_in[0];
    const int*   ei  = (const int*)d_in[1];
    const float* Wl1 = (const float*)d_in[2];
    const float* bl1 = (const float*)d_in[3];
    const float* Wr1 = (const float*)d_in[4];
    const float* Wl2 = (const float*)d_in[5];
    const float* bl2 = (const float*)d_in[6];
    const float* Wr2 = (const float*)d_in[7];
    float* out = (float*)d_out;

    int N = in_sizes[0] / D;       // 100000
    int E = in_sizes[1] / 2;       // 1250000

    float *agg, *h, *cnt;
    cudaGetSymbolAddress((void**)&agg, g_agg);
    cudaGetSymbolAddress((void**)&h,   g_h);
    cudaGetSymbolAddress((void**)&cnt, g_cnt);

    int nd4 = N * D / 4;
    int nc4 = (N + 3) / 4;         // cnt buffer (N floats; global is big enough)
    int zb1 = (nd4 + 255) / 256;
    int zb2 = (nc4 + 255) / 256;

    int scatter_threads = E * 16;
    int sb = (scatter_threads + 255) / 256;

    int tb = (N + 15) / 16;

    // ---- Layer 1 ----
    zero_kernel<<<zb1, 256>>>((float4*)agg, nd4);
    zero_kernel<<<zb2, 256>>>((float4*)cnt, nc4);
    scatter_kernel<<<sb, 256>>>((const float4*)x, ei, agg, cnt, E, 1);
    transform_kernel<<<tb, 128>>>(x, agg, cnt, Wl1, bl1, Wr1, h, N, 1);

    // ---- Layer 2 ----
    zero_kernel<<<zb1, 256>>>((float4*)agg, nd4);
    scatter_kernel<<<sb, 256>>>((const float4*)h, ei, agg, cnt, E, 0);
    transform_kernel<<<tb, 128>>>(h, agg, cnt, Wl2, bl2, Wr2, out, N, 0);
}

// round 2
// speedup vs baseline: 1.3654x; 1.3654x over previous
#include <cuda_runtime.h>
#include <cuda_bf16.h>

#define MAX_N 100000
#define MAX_E 1250000
#define D 64
#define SCAN_BLK 2048   // elements per scan block (256 thr x 8)
#define MAX_SCAN_BLKS 64

// Scratch (device globals; no allocation allowed).
__device__ float g_mean[MAX_N * D];
__device__ float g_h[MAX_N * D];
__device__ int   g_cnt[MAX_N];
__device__ int   g_off[MAX_N];
__device__ int   g_pos[MAX_N];
__device__ int   g_csr[MAX_E];
__device__ int   g_blk[MAX_SCAN_BLKS];

// ---------------------------------------------------------------------------
__global__ void zero_int_kernel(int* __restrict__ p, int n) {
    int i = blockIdx.x * blockDim.x + threadIdx.x;
    if (i < n) p[i] = 0;
}

// Histogram of dst degrees.
__global__ void hist_kernel(const int* __restrict__ ei, int* __restrict__ cnt, int E) {
    int e = blockIdx.x * blockDim.x + threadIdx.x;
    if (e < E) atomicAdd(&cnt[ei[E + e]], 1);
}

// Scan stage 1: per-block exclusive prefix + block totals. 256 thr, 8 elems each.
__global__ __launch_bounds__(256)
void scan_k1(const int* __restrict__ cnt, int* __restrict__ off,
             int* __restrict__ blk, int n) {
    __shared__ int warp_excl[8];
    int t = threadIdx.x;
    int lane = t & 31, w = t >> 5;
    int base = blockIdx.x * SCAN_BLK + t * 8;
    int v[8];
    int s = 0;
#pragma unroll
    for (int q = 0; q < 8; q++) {
        int idx = base + q;
        v[q] = (idx < n) ? cnt[idx] : 0;
        s += v[q];
    }
    // warp inclusive scan of thread sums
    int ps = s;
#pragma unroll
    for (int d = 1; d < 32; d <<= 1) {
        int o = __shfl_up_sync(0xffffffffu, ps, d);
        if (lane >= d) ps += o;
    }
    if (lane == 31) warp_excl[w] = ps;  // warp totals (temp)
    __syncthreads();
    if (w == 0 && lane < 8) {
        int ws = warp_excl[lane];
        int pw = ws;
#pragma unroll
        for (int d = 1; d < 8; d <<= 1) {
            int o = __shfl_up_sync(0xffu, pw, d);
            if (lane >= d) pw += o;
        }
        warp_excl[lane] = pw - ws;  // exclusive warp prefix
    }
    __syncthreads();
    int excl = warp_excl[w] + (ps - s);  // exclusive prefix for this thread
    int run = excl;
#pragma unroll
    for (int q = 0; q < 8; q++) {
        int idx = base + q;
        if (idx < n) off[idx] = run;
        run += v[q];
    }
    if (t == 255) blk[blockIdx.x] = excl + s;  // block total
}

// Scan stage 2: exclusive scan of block totals (single block, <=64 blocks).
__global__ void scan_k2(int* __restrict__ blk, int nb) {
    __shared__ int sm[MAX_SCAN_BLKS];
    int t = threadIdx.x;
    int v = (t < nb) ? blk[t] : 0;
    sm[t] = v;
    __syncthreads();
    for (int d = 1; d < MAX_SCAN_BLKS; d <<= 1) {
        int o = (t >= d) ? sm[t - d] : 0;
        __syncthreads();
        sm[t] += o;
        __syncthreads();
    }
    if (t < nb) blk[t] = sm[t] - v;  // exclusive
}

// Scan stage 3: add block offsets; duplicate into pos (fill cursor).
__global__ void scan_k3(int* __restrict__ off, const int* __restrict__ blk,
                        int* __restrict__ pos, int n) {
    int i = blockIdx.x * blockDim.x + threadIdx.x;
    if (i < n) {
        int o = off[i] + blk[i >> 11];  // SCAN_BLK == 2048
        off[i] = o;
        pos[i] = o;
    }
}

// CSR fill: slot per edge via atomic cursor.
__global__ void fill_kernel(const int* __restrict__ ei, int* __restrict__ pos,
                            int* __restrict__ csr, int E) {
    int e = blockIdx.x * blockDim.x + threadIdx.x;
    if (e < E) {
        int dst = ei[E + e];
        int p = atomicAdd(&pos[dst], 1);
        csr[p] = ei[e];
    }
}

// ---------------------------------------------------------------------------
// Aggregate: mean[node] = (1/max(cnt,1)) * sum_{i in CSR[node]} x[csr[i]]
// 16 threads per node, each owns one float4 chunk of the row. No atomics.
// ---------------------------------------------------------------------------
__global__ __launch_bounds__(256)
void aggregate_kernel(const float4* __restrict__ x4,
                      const int* __restrict__ off,
                      const int* __restrict__ cnt,
                      const int* __restrict__ csr,
                      float4* __restrict__ mean4, int n) {
    int tid = blockIdx.x * blockDim.x + threadIdx.x;
    int node = tid >> 4;
    if (node >= n) return;
    int j = tid & 15;
    int s = off[node];
    int c = cnt[node];
    int e = s + c;

    float4 a0 = make_float4(0.f, 0.f, 0.f, 0.f);
    float4 a1 = make_float4(0.f, 0.f, 0.f, 0.f);
    int i = s;
    for (; i + 2 <= e; i += 2) {
        int s0 = csr[i];
        int s1 = csr[i + 1];
        float4 v0 = x4[s0 * 16 + j];
        float4 v1 = x4[s1 * 16 + j];
        a0.x += v0.x; a0.y += v0.y; a0.z += v0.z; a0.w += v0.w;
        a1.x += v1.x; a1.y += v1.y; a1.z += v1.z; a1.w += v1.w;
    }
    if (i < e) {
        float4 v = x4[csr[i] * 16 + j];
        a0.x += v.x; a0.y += v.y; a0.z += v.z; a0.w += v.w;
    }
    float inv = 1.0f / fmaxf((float)c, 1.0f);
    a0.x = (a0.x + a1.x) * inv;
    a0.y = (a0.y + a1.y) * inv;
    a0.z = (a0.z + a1.z) * inv;
    a0.w = (a0.w + a1.w) * inv;
    mean4[node * 16 + j] = a0;
}

// ---------------------------------------------------------------------------
// Transform: out[i] = act( mean[i] @ W_l + b_l + xin[i] @ W_r )
// 32 nodes per block, 128 threads. Thread = 4 contiguous nodes x 4 cols.
// Node rows staged TRANSPOSED ([k][node]) so inner loop is all LDS.128.
// ---------------------------------------------------------------------------
#define TN 32
__global__ __launch_bounds__(128)
void transform_kernel(const float* __restrict__ xin,
                      const float* __restrict__ mean,
                      const float* __restrict__ Wl,
                      const float* __restrict__ bl,
                      const float* __restrict__ Wr,
                      float* __restrict__ out,
                      int n, int do_relu) {
    __shared__ float sWl[D * D];     // 16 KB
    __shared__ float sWr[D * D];     // 16 KB
    __shared__ float sMt[D * TN];    // 8 KB, [k][node]
    __shared__ float sXt[D * TN];    // 8 KB, [k][node]
    __shared__ float sB[D];

    int t = threadIdx.x;
    for (int i = t; i < 1024; i += 128) {
        ((float4*)sWl)[i] = ((const float4*)Wl)[i];
        ((float4*)sWr)[i] = ((const float4*)Wr)[i];
    }
    if (t < D) sB[t] = bl[t];

    int base = blockIdx.x * TN;
    // Stage 32 nodes x 16 float4 chunks, transposing into [k][node].
    for (int i = t; i < TN * 16; i += 128) {
        int local = i & (TN - 1);
        int j = i >> 5;  // float4 chunk (k = 4j..4j+3)
        int node = base + local;
        float4 mv, xv;
        if (node < n) {
            mv = ((const float4*)mean)[node * 16 + j];
            xv = ((const float4*)xin)[node * 16 + j];
        } else {
            mv = make_float4(0.f, 0.f, 0.f, 0.f);
            xv = mv;
        }
        sMt[(4 * j + 0) * TN + local] = mv.x;
        sMt[(4 * j + 1) * TN + local] = mv.y;
        sMt[(4 * j + 2) * TN + local] = mv.z;
        sMt[(4 * j + 3) * TN + local] = mv.w;
        sXt[(4 * j + 0) * TN + local] = xv.x;
        sXt[(4 * j + 1) * TN + local] = xv.y;
        sXt[(4 * j + 2) * TN + local] = xv.z;
        sXt[(4 * j + 3) * TN + local] = xv.w;
    }
    __syncthreads();

    int cg = t & 15;        // column group: cols 4*cg..4*cg+3
    int nd = t >> 4;        // 0..7
    int c0 = cg * 4;
    int nb = nd * 4;        // nodes nb..nb+3 (contiguous)

    float4 bias = *(float4*)&sB[c0];
    float4 acc[4];
#pragma unroll
    for (int q = 0; q < 4; q++) acc[q] = bias;

#pragma unroll
    for (int k = 0; k < D; k++) {
        float4 wl = *(float4*)&sWl[k * D + c0];
        float4 wr = *(float4*)&sWr[k * D + c0];
        float4 m4 = *(float4*)&sMt[k * TN + nb];
        float4 x4 = *(float4*)&sXt[k * TN + nb];
        float mv[4] = {m4.x, m4.y, m4.z, m4.w};
        float xv[4] = {x4.x, x4.y, x4.z, x4.w};
#pragma unroll
        for (int q = 0; q < 4; q++) {
            acc[q].x = fmaf(mv[q], wl.x, acc[q].x);
            acc[q].y = fmaf(mv[q], wl.y, acc[q].y);
            acc[q].z = fmaf(mv[q], wl.z, acc[q].z);
            acc[q].w = fmaf(mv[q], wl.w, acc[q].w);
            acc[q].x = fmaf(xv[q], wr.x, acc[q].x);
            acc[q].y = fmaf(xv[q], wr.y, acc[q].y);
            acc[q].z = fmaf(xv[q], wr.z, acc[q].z);
            acc[q].w = fmaf(xv[q], wr.w, acc[q].w);
        }
    }

    if (do_relu) {
#pragma unroll
        for (int q = 0; q < 4; q++) {
            acc[q].x = fmaxf(acc[q].x, 0.f);
            acc[q].y = fmaxf(acc[q].y, 0.f);
            acc[q].z = fmaxf(acc[q].z, 0.f);
            acc[q].w = fmaxf(acc[q].w, 0.f);
        }
    }

#pragma unroll
    for (int q = 0; q < 4; q++) {
        int node = base + nb + q;
        if (node < n) *(float4*)&out[node * D + c0] = acc[q];
    }
}

// ---------------------------------------------------------------------------
extern "C" void kernel_launch(void* const* d_in, const int* in_sizes, int n_in,
                              void* d_out, int out_size) {
    const float* x   = (const float*)d_in[0];
    const int*   ei  = (const int*)d_in[1];
    const float* Wl1 = (const float*)d_in[2];
    const float* bl1 = (const float*)d_in[3];
    const float* Wr1 = (const float*)d_in[4];
    const float* Wl2 = (const float*)d_in[5];
    const float* bl2 = (const float*)d_in[6];
    const float* Wr2 = (const float*)d_in[7];
    float* out = (float*)d_out;

    int N = in_sizes[0] / D;   // 100000
    int E = in_sizes[1] / 2;   // 1250000

    float *mean, *h;
    int *cnt, *off, *pos, *csr, *blk;
    cudaGetSymbolAddress((void**)&mean, g_mean);
    cudaGetSymbolAddress((void**)&h,    g_h);
    cudaGetSymbolAddress((void**)&cnt,  g_cnt);
    cudaGetSymbolAddress((void**)&off,  g_off);
    cudaGetSymbolAddress((void**)&pos,  g_pos);
    cudaGetSymbolAddress((void**)&csr,  g_csr);
    cudaGetSymbolAddress((void**)&blk,  g_blk);

    int nb_scan = (N + SCAN_BLK - 1) / SCAN_BLK;   // 49

    // ---- CSR build (once; reused by both layers) ----
    zero_int_kernel<<<(N + 255) / 256, 256>>>(cnt, N);
    hist_kernel<<<(E + 255) / 256, 256>>>(ei, cnt, E);
    scan_k1<<<nb_scan, 256>>>(cnt, off, blk, N);
    scan_k2<<<1, MAX_SCAN_BLKS>>>(blk, nb_scan);
    scan_k3<<<(N + 255) / 256, 256>>>(off, blk, pos, N);
    fill_kernel<<<(E + 255) / 256, 256>>>(ei, pos, csr, E);

    int ab = (N * 16 + 255) / 256;
    int tb = (N + TN - 1) / TN;

    // ---- Layer 1 ----
    aggregate_kernel<<<ab, 256>>>((const float4*)x, off, cnt, csr,
                                  (float4*)mean, N);
    transform_kernel<<<tb, 128>>>(x, mean, Wl1, bl1, Wr1, h, N, 1);

    // ---- Layer 2 ----
    aggregate_kernel<<<ab, 256>>>((const float4*)h, off, cnt, csr,
                                  (float4*)mean, N);
    transform_kernel<<<tb, 128>>>(h, mean, Wl2, bl2, Wr2, out, N, 0);
}